// round 1
// baseline (speedup 1.0000x reference)
#include <cuda_runtime.h>
#include <math.h>

// Problem dims
#define BD   2
#define TD   2048
#define CD   1024
#define HN   16
#define HD   64
#define DFFD 4096
#define NT   (BD * TD)   // 4096 tokens

// ---------------------------------------------------------------------------
// Scratch (device globals; no allocation allowed)
// ---------------------------------------------------------------------------
__device__ float g_t  [(size_t)NT * CD];    // LN output / reused for t2
__device__ float g_q  [(size_t)NT * CD];
__device__ float g_k  [(size_t)NT * CD];
__device__ float g_v  [(size_t)NT * CD];
__device__ float g_ctx[(size_t)NT * CD];
__device__ float g_x2 [(size_t)NT * CD];    // x + attn_out
__device__ float g_h  [(size_t)NT * DFFD];  // FFN hidden

// ---------------------------------------------------------------------------
// Fused double LayerNorm: out = LN_b(LN_a(x)); one block per row (1024 cols)
// ---------------------------------------------------------------------------
__global__ __launch_bounds__(256) void ln2_kernel(
    const float* __restrict__ x,
    const float* __restrict__ ga, const float* __restrict__ ba,
    const float* __restrict__ gb, const float* __restrict__ bb,
    float* __restrict__ out)
{
    __shared__ float red[16];
    __shared__ float bc[2];
    const int row = blockIdx.x, tid = threadIdx.x;
    const float4 v = *(const float4*)(x + (size_t)row * CD + tid * 4);

    float s  = v.x + v.y + v.z + v.w;
    float s2 = v.x*v.x + v.y*v.y + v.z*v.z + v.w*v.w;
    #pragma unroll
    for (int o = 16; o; o >>= 1) {
        s  += __shfl_xor_sync(~0u, s,  o);
        s2 += __shfl_xor_sync(~0u, s2, o);
    }
    if ((tid & 31) == 0) { red[(tid >> 5)*2] = s; red[(tid >> 5)*2 + 1] = s2; }
    __syncthreads();
    if (tid == 0) {
        float a = 0.f, b2 = 0.f;
        #pragma unroll
        for (int w = 0; w < 8; w++) { a += red[w*2]; b2 += red[w*2 + 1]; }
        float mu  = a * (1.f / CD);
        float var = b2 * (1.f / CD) - mu * mu;
        bc[0] = mu; bc[1] = rsqrtf(var + 1e-5f);
    }
    __syncthreads();
    float mu = bc[0], rstd = bc[1];
    __syncthreads();  // before red reuse

    const float4 g4 = *(const float4*)(ga + tid * 4);
    const float4 b4 = *(const float4*)(ba + tid * 4);
    float y[4];
    y[0] = (v.x - mu) * rstd * g4.x + b4.x;
    y[1] = (v.y - mu) * rstd * g4.y + b4.y;
    y[2] = (v.z - mu) * rstd * g4.z + b4.z;
    y[3] = (v.w - mu) * rstd * g4.w + b4.w;

    s  = y[0] + y[1] + y[2] + y[3];
    s2 = y[0]*y[0] + y[1]*y[1] + y[2]*y[2] + y[3]*y[3];
    #pragma unroll
    for (int o = 16; o; o >>= 1) {
        s  += __shfl_xor_sync(~0u, s,  o);
        s2 += __shfl_xor_sync(~0u, s2, o);
    }
    if ((tid & 31) == 0) { red[(tid >> 5)*2] = s; red[(tid >> 5)*2 + 1] = s2; }
    __syncthreads();
    if (tid == 0) {
        float a = 0.f, b2 = 0.f;
        #pragma unroll
        for (int w = 0; w < 8; w++) { a += red[w*2]; b2 += red[w*2 + 1]; }
        float mu2  = a * (1.f / CD);
        float var2 = b2 * (1.f / CD) - mu2 * mu2;
        bc[0] = mu2; bc[1] = rsqrtf(var2 + 1e-5f);
    }
    __syncthreads();
    mu = bc[0]; rstd = bc[1];

    const float4 g24 = *(const float4*)(gb + tid * 4);
    const float4 b24 = *(const float4*)(bb + tid * 4);
    float4 o;
    o.x = (y[0] - mu) * rstd * g24.x + b24.x;
    o.y = (y[1] - mu) * rstd * g24.y + b24.y;
    o.z = (y[2] - mu) * rstd * g24.z + b24.z;
    o.w = (y[3] - mu) * rstd * g24.w + b24.w;
    *(float4*)(out + (size_t)row * CD + tid * 4) = o;
}

// Single LayerNorm
__global__ __launch_bounds__(256) void ln1_kernel(
    const float* __restrict__ x,
    const float* __restrict__ g, const float* __restrict__ b,
    float* __restrict__ out)
{
    __shared__ float red[16];
    __shared__ float bc[2];
    const int row = blockIdx.x, tid = threadIdx.x;
    const float4 v = *(const float4*)(x + (size_t)row * CD + tid * 4);

    float s  = v.x + v.y + v.z + v.w;
    float s2 = v.x*v.x + v.y*v.y + v.z*v.z + v.w*v.w;
    #pragma unroll
    for (int o = 16; o; o >>= 1) {
        s  += __shfl_xor_sync(~0u, s,  o);
        s2 += __shfl_xor_sync(~0u, s2, o);
    }
    if ((tid & 31) == 0) { red[(tid >> 5)*2] = s; red[(tid >> 5)*2 + 1] = s2; }
    __syncthreads();
    if (tid == 0) {
        float a = 0.f, b2 = 0.f;
        #pragma unroll
        for (int w = 0; w < 8; w++) { a += red[w*2]; b2 += red[w*2 + 1]; }
        float mu  = a * (1.f / CD);
        float var = b2 * (1.f / CD) - mu * mu;
        bc[0] = mu; bc[1] = rsqrtf(var + 1e-5f);
    }
    __syncthreads();
    const float mu = bc[0], rstd = bc[1];
    const float4 g4 = *(const float4*)(g + tid * 4);
    const float4 b4 = *(const float4*)(b + tid * 4);
    float4 o;
    o.x = (v.x - mu) * rstd * g4.x + b4.x;
    o.y = (v.y - mu) * rstd * g4.y + b4.y;
    o.z = (v.z - mu) * rstd * g4.z + b4.z;
    o.w = (v.w - mu) * rstd * g4.w + b4.w;
    *(float4*)(out + (size_t)row * CD + tid * 4) = o;
}

// ---------------------------------------------------------------------------
// SGEMM: C[M,N] = act(A[M,K] @ W[K,N] + bias) (+ res)
// 128x128 tile, BK=8, 256 threads, 8x8 micro-tile. Dims multiple of 128/8.
// act: 0 = none, 1 = SiLU
// ---------------------------------------------------------------------------
__global__ __launch_bounds__(256) void gemm_kernel(
    const float* __restrict__ A, const float* __restrict__ W,
    const float* __restrict__ bias, const float* __restrict__ res,
    float* __restrict__ Cc, int M, int N, int K, int act)
{
    __shared__ float As[8][128];
    __shared__ float Bs[8][128];
    const int tid = threadIdx.x;
    const int bm = blockIdx.y * 128;
    const int bn = blockIdx.x * 128;
    const int ty = tid >> 4, tx = tid & 15;

    float acc[8][8];
    #pragma unroll
    for (int i = 0; i < 8; i++)
        #pragma unroll
        for (int j = 0; j < 8; j++) acc[i][j] = 0.f;

    const int arow  = tid >> 1;
    const int acol4 = (tid & 1) * 4;
    const int brow  = tid >> 5;
    const int bcol4 = (tid & 31) * 4;

    for (int k0 = 0; k0 < K; k0 += 8) {
        float4 av = *(const float4*)&A[(size_t)(bm + arow) * K + k0 + acol4];
        As[acol4 + 0][arow] = av.x;
        As[acol4 + 1][arow] = av.y;
        As[acol4 + 2][arow] = av.z;
        As[acol4 + 3][arow] = av.w;
        *(float4*)&Bs[brow][bcol4] =
            *(const float4*)&W[(size_t)(k0 + brow) * N + bn + bcol4];
        __syncthreads();
        #pragma unroll
        for (int k = 0; k < 8; k++) {
            float a[8], b[8];
            #pragma unroll
            for (int i = 0; i < 8; i++) a[i] = As[k][ty * 8 + i];
            #pragma unroll
            for (int j = 0; j < 8; j++) b[j] = Bs[k][tx * 8 + j];
            #pragma unroll
            for (int i = 0; i < 8; i++)
                #pragma unroll
                for (int j = 0; j < 8; j++) acc[i][j] += a[i] * b[j];
        }
        __syncthreads();
    }

    // epilogue
    #pragma unroll
    for (int i = 0; i < 8; i++) {
        const size_t off = (size_t)(bm + ty * 8 + i) * N + bn + tx * 8;
        #pragma unroll
        for (int jj = 0; jj < 8; jj += 4) {
            float4 o;
            o.x = acc[i][jj + 0] + bias[bn + tx * 8 + jj + 0];
            o.y = acc[i][jj + 1] + bias[bn + tx * 8 + jj + 1];
            o.z = acc[i][jj + 2] + bias[bn + tx * 8 + jj + 2];
            o.w = acc[i][jj + 3] + bias[bn + tx * 8 + jj + 3];
            if (act) {
                o.x *= 1.f / (1.f + __expf(-o.x));
                o.y *= 1.f / (1.f + __expf(-o.y));
                o.z *= 1.f / (1.f + __expf(-o.z));
                o.w *= 1.f / (1.f + __expf(-o.w));
            }
            if (res) {
                float4 r = *(const float4*)(res + off + jj);
                o.x += r.x; o.y += r.y; o.z += r.z; o.w += r.w;
            }
            *(float4*)(Cc + off + jj) = o;
        }
    }
}

// ---------------------------------------------------------------------------
// Flash attention (fp32, causal). Q/K/V layout: [token][C], head h at cols
// h*64..h*64+63. Grid: (T/64, B*H). Block 256 threads. Output same layout.
// ---------------------------------------------------------------------------
#define ATTN_SMEM ((64*64*3 + 64*65) * 4)

__global__ __launch_bounds__(256) void attn_kernel(
    const float* __restrict__ Q, const float* __restrict__ Kg,
    const float* __restrict__ Vg, float* __restrict__ O)
{
    extern __shared__ float smem[];
    float* Qt = smem;               // [d][q]  (d-major)
    float* Kt = Qt + 64 * 64;       // [d][k]
    float* Vs = Kt + 64 * 64;       // [k][d]
    float* Ps = Vs + 64 * 64;       // [q][65] padded

    const int bh = blockIdx.y;
    const int b = bh >> 4, h = bh & 15;
    const int q0 = blockIdx.x * 64;
    const int tid = threadIdx.x;
    const int ty = tid >> 4, tx = tid & 15;
    const size_t base = (size_t)b * TD * CD + (size_t)h * HD;

    // load Q transposed
    for (int idx = tid; idx < 64 * 64; idx += 256) {
        const int r = idx >> 6, d = idx & 63;
        Qt[d * 64 + r] = Q[base + (size_t)(q0 + r) * CD + d];
    }

    float m[4], l[4], acc[4][4];
    #pragma unroll
    for (int i = 0; i < 4; i++) {
        m[i] = -1e30f; l[i] = 0.f;
        #pragma unroll
        for (int j = 0; j < 4; j++) acc[i][j] = 0.f;
    }

    const int ktiles = blockIdx.x + 1;
    for (int kt = 0; kt < ktiles; kt++) {
        const int k0 = kt * 64;
        __syncthreads();  // protect Kt/Vs/Ps (and Qt on first iter)
        for (int idx = tid; idx < 64 * 64; idx += 256) {
            const int r = idx >> 6, d = idx & 63;
            const size_t goff = base + (size_t)(k0 + r) * CD + d;
            Kt[d * 64 + r] = Kg[goff];
            Vs[idx]        = Vg[goff];
        }
        __syncthreads();

        // S = Q K^T * scale
        float s[4][4];
        #pragma unroll
        for (int i = 0; i < 4; i++)
            #pragma unroll
            for (int j = 0; j < 4; j++) s[i][j] = 0.f;
        for (int d = 0; d < 64; d++) {
            float a[4], bb[4];
            #pragma unroll
            for (int i = 0; i < 4; i++) a[i]  = Qt[d * 64 + ty * 4 + i];
            #pragma unroll
            for (int j = 0; j < 4; j++) bb[j] = Kt[d * 64 + tx * 4 + j];
            #pragma unroll
            for (int i = 0; i < 4; i++)
                #pragma unroll
                for (int j = 0; j < 4; j++) s[i][j] += a[i] * bb[j];
        }
        #pragma unroll
        for (int i = 0; i < 4; i++)
            #pragma unroll
            for (int j = 0; j < 4; j++) s[i][j] *= 0.125f;  // 1/sqrt(64)

        if (kt == blockIdx.x) {  // diagonal tile: causal mask
            #pragma unroll
            for (int i = 0; i < 4; i++)
                #pragma unroll
                for (int j = 0; j < 4; j++)
                    if (k0 + tx * 4 + j > q0 + ty * 4 + i) s[i][j] = -1e30f;
        }

        // online softmax update
        #pragma unroll
        for (int i = 0; i < 4; i++) {
            float rm = fmaxf(fmaxf(s[i][0], s[i][1]), fmaxf(s[i][2], s[i][3]));
            #pragma unroll
            for (int o = 8; o; o >>= 1) rm = fmaxf(rm, __shfl_xor_sync(~0u, rm, o));
            const float mn = fmaxf(m[i], rm);
            float rs = 0.f;
            #pragma unroll
            for (int j = 0; j < 4; j++) {
                const float p = __expf(s[i][j] - mn);
                Ps[(ty * 4 + i) * 65 + tx * 4 + j] = p;
                rs += p;
            }
            #pragma unroll
            for (int o = 8; o; o >>= 1) rs += __shfl_xor_sync(~0u, rs, o);
            const float fac = __expf(m[i] - mn);
            l[i] = l[i] * fac + rs;
            #pragma unroll
            for (int j = 0; j < 4; j++) acc[i][j] *= fac;
            m[i] = mn;
        }
        __syncthreads();  // Ps visible

        // O += P @ V
        for (int k = 0; k < 64; k++) {
            float p[4], vv[4];
            #pragma unroll
            for (int i = 0; i < 4; i++) p[i]  = Ps[(ty * 4 + i) * 65 + k];
            #pragma unroll
            for (int j = 0; j < 4; j++) vv[j] = Vs[k * 64 + tx * 4 + j];
            #pragma unroll
            for (int i = 0; i < 4; i++)
                #pragma unroll
                for (int j = 0; j < 4; j++) acc[i][j] += p[i] * vv[j];
        }
    }

    // epilogue: normalize and write [token][C]
    #pragma unroll
    for (int i = 0; i < 4; i++) {
        const float inv = 1.f / l[i];
        const size_t off = (size_t)(b * TD + q0 + ty * 4 + i) * CD + h * HD + tx * 4;
        #pragma unroll
        for (int j = 0; j < 4; j++) O[off + j] = acc[i][j] * inv;
    }
}

// ---------------------------------------------------------------------------
// Launch
// ---------------------------------------------------------------------------
extern "C" void kernel_launch(void* const* d_in, const int* in_sizes, int n_in,
                              void* d_out, int out_size)
{
    const float* x      = (const float*)d_in[0];
    const float* ln_a_g = (const float*)d_in[1];
    const float* ln_a_b = (const float*)d_in[2];
    const float* ln_b_g = (const float*)d_in[3];
    const float* ln_b_b = (const float*)d_in[4];
    const float* ln_c_g = (const float*)d_in[5];
    const float* ln_c_b = (const float*)d_in[6];
    const float* Wq = (const float*)d_in[7];  const float* bq = (const float*)d_in[8];
    const float* Wk = (const float*)d_in[9];  const float* bk = (const float*)d_in[10];
    const float* Wv = (const float*)d_in[11]; const float* bv = (const float*)d_in[12];
    const float* Wo = (const float*)d_in[13]; const float* bo = (const float*)d_in[14];
    const float* We = (const float*)d_in[15]; const float* be = (const float*)d_in[16];
    const float* Wd = (const float*)d_in[17]; const float* bd = (const float*)d_in[18];
    float* out = (float*)d_out;

    float *t, *q, *k, *v, *ctx, *x2, *h;
    cudaGetSymbolAddress((void**)&t,   g_t);
    cudaGetSymbolAddress((void**)&q,   g_q);
    cudaGetSymbolAddress((void**)&k,   g_k);
    cudaGetSymbolAddress((void**)&v,   g_v);
    cudaGetSymbolAddress((void**)&ctx, g_ctx);
    cudaGetSymbolAddress((void**)&x2,  g_x2);
    cudaGetSymbolAddress((void**)&h,   g_h);

    cudaFuncSetAttribute(attn_kernel, cudaFuncAttributeMaxDynamicSharedMemorySize,
                         ATTN_SMEM);

    // 1. t = LN_b(LN_a(x))
    ln2_kernel<<<NT, 256>>>(x, ln_a_g, ln_a_b, ln_b_g, ln_b_b, t);

    // 2. QKV projections
    {
        dim3 grid(CD / 128, NT / 128);
        gemm_kernel<<<grid, 256>>>(t, Wq, bq, nullptr, q, NT, CD, CD, 0);
        gemm_kernel<<<grid, 256>>>(t, Wk, bk, nullptr, k, NT, CD, CD, 0);
        gemm_kernel<<<grid, 256>>>(t, Wv, bv, nullptr, v, NT, CD, CD, 0);
    }

    // 3. causal attention
    {
        dim3 grid(TD / 64, BD * HN);
        attn_kernel<<<grid, 256, ATTN_SMEM>>>(q, k, v, ctx);
    }

    // 4. x2 = x + ctx @ Wo + bo
    {
        dim3 grid(CD / 128, NT / 128);
        gemm_kernel<<<grid, 256>>>(ctx, Wo, bo, x, x2, NT, CD, CD, 0);
    }

    // 5. t = LN_c(x2)
    ln1_kernel<<<NT, 256>>>(x2, ln_c_g, ln_c_b, t);

    // 6. h = silu(t @ We + be)
    {
        dim3 grid(DFFD / 128, NT / 128);
        gemm_kernel<<<grid, 256>>>(t, We, be, nullptr, h, NT, DFFD, CD, 1);
    }

    // 7. out = x2 + h @ Wd + bd
    {
        dim3 grid(CD / 128, NT / 128);
        gemm_kernel<<<grid, 256>>>(h, Wd, bd, x2, out, NT, CD, DFFD, 0);
    }
}

// round 2
// speedup vs baseline: 2.1243x; 2.1243x over previous
#include <cuda_runtime.h>
#include <math.h>
#include <stdint.h>

// Problem dims
#define BD   2
#define TD   2048
#define CD   1024
#define HN   16
#define HD   64
#define DFFD 4096
#define NT   (BD * TD)   // 4096 tokens

// ---------------------------------------------------------------------------
// Scratch (device globals; no allocation allowed)
// ---------------------------------------------------------------------------
__device__ float g_t  [(size_t)NT * CD];
__device__ float g_q  [(size_t)NT * CD];
__device__ float g_k  [(size_t)NT * CD];
__device__ float g_v  [(size_t)NT * CD];
__device__ float g_ctx[(size_t)NT * CD];
__device__ float g_x2 [(size_t)NT * CD];
__device__ float g_h  [(size_t)NT * DFFD];

// ---------------------------------------------------------------------------
// Helpers
// ---------------------------------------------------------------------------
__device__ __forceinline__ uint32_t f2tf32(float f) {
    uint32_t u;
    asm("cvt.rna.tf32.f32 %0, %1;" : "=r"(u) : "f"(f));
    return u;
}

__device__ __forceinline__ void cp16(uint32_t smem_dst, const void* gptr) {
    asm volatile("cp.async.cg.shared.global [%0], [%1], 16;\n"
                 :: "r"(smem_dst), "l"(gptr));
}
__device__ __forceinline__ void cp_commit() {
    asm volatile("cp.async.commit_group;\n" ::: "memory");
}
template <int N>
__device__ __forceinline__ void cp_wait() {
    asm volatile("cp.async.wait_group %0;\n" :: "n"(N) : "memory");
}

__device__ __forceinline__ void mma_tf32(float* c, const uint32_t* a, const uint32_t* b) {
    asm volatile(
        "mma.sync.aligned.m16n8k8.row.col.f32.tf32.tf32.f32 "
        "{%0,%1,%2,%3},{%4,%5,%6,%7},{%8,%9},{%0,%1,%2,%3};"
        : "+f"(c[0]), "+f"(c[1]), "+f"(c[2]), "+f"(c[3])
        : "r"(a[0]), "r"(a[1]), "r"(a[2]), "r"(a[3]), "r"(b[0]), "r"(b[1]));
}

// ---------------------------------------------------------------------------
// Fused double LayerNorm: out = LN_b(LN_a(x)); one block per row
// ---------------------------------------------------------------------------
__global__ __launch_bounds__(256) void ln2_kernel(
    const float* __restrict__ x,
    const float* __restrict__ ga, const float* __restrict__ ba,
    const float* __restrict__ gb, const float* __restrict__ bb,
    float* __restrict__ out)
{
    __shared__ float red[16];
    __shared__ float bc[2];
    const int row = blockIdx.x, tid = threadIdx.x;
    const float4 v = *(const float4*)(x + (size_t)row * CD + tid * 4);

    float s  = v.x + v.y + v.z + v.w;
    float s2 = v.x*v.x + v.y*v.y + v.z*v.z + v.w*v.w;
    #pragma unroll
    for (int o = 16; o; o >>= 1) {
        s  += __shfl_xor_sync(~0u, s,  o);
        s2 += __shfl_xor_sync(~0u, s2, o);
    }
    if ((tid & 31) == 0) { red[(tid >> 5)*2] = s; red[(tid >> 5)*2 + 1] = s2; }
    __syncthreads();
    if (tid == 0) {
        float a = 0.f, b2 = 0.f;
        #pragma unroll
        for (int w = 0; w < 8; w++) { a += red[w*2]; b2 += red[w*2 + 1]; }
        float mu  = a * (1.f / CD);
        float var = b2 * (1.f / CD) - mu * mu;
        bc[0] = mu; bc[1] = rsqrtf(var + 1e-5f);
    }
    __syncthreads();
    float mu = bc[0], rstd = bc[1];
    __syncthreads();

    const float4 g4 = *(const float4*)(ga + tid * 4);
    const float4 b4 = *(const float4*)(ba + tid * 4);
    float y[4];
    y[0] = (v.x - mu) * rstd * g4.x + b4.x;
    y[1] = (v.y - mu) * rstd * g4.y + b4.y;
    y[2] = (v.z - mu) * rstd * g4.z + b4.z;
    y[3] = (v.w - mu) * rstd * g4.w + b4.w;

    s  = y[0] + y[1] + y[2] + y[3];
    s2 = y[0]*y[0] + y[1]*y[1] + y[2]*y[2] + y[3]*y[3];
    #pragma unroll
    for (int o = 16; o; o >>= 1) {
        s  += __shfl_xor_sync(~0u, s,  o);
        s2 += __shfl_xor_sync(~0u, s2, o);
    }
    if ((tid & 31) == 0) { red[(tid >> 5)*2] = s; red[(tid >> 5)*2 + 1] = s2; }
    __syncthreads();
    if (tid == 0) {
        float a = 0.f, b2 = 0.f;
        #pragma unroll
        for (int w = 0; w < 8; w++) { a += red[w*2]; b2 += red[w*2 + 1]; }
        float mu2  = a * (1.f / CD);
        float var2 = b2 * (1.f / CD) - mu2 * mu2;
        bc[0] = mu2; bc[1] = rsqrtf(var2 + 1e-5f);
    }
    __syncthreads();
    mu = bc[0]; rstd = bc[1];

    const float4 g24 = *(const float4*)(gb + tid * 4);
    const float4 b24 = *(const float4*)(bb + tid * 4);
    float4 o;
    o.x = (y[0] - mu) * rstd * g24.x + b24.x;
    o.y = (y[1] - mu) * rstd * g24.y + b24.y;
    o.z = (y[2] - mu) * rstd * g24.z + b24.z;
    o.w = (y[3] - mu) * rstd * g24.w + b24.w;
    *(float4*)(out + (size_t)row * CD + tid * 4) = o;
}

__global__ __launch_bounds__(256) void ln1_kernel(
    const float* __restrict__ x,
    const float* __restrict__ g, const float* __restrict__ b,
    float* __restrict__ out)
{
    __shared__ float red[16];
    __shared__ float bc[2];
    const int row = blockIdx.x, tid = threadIdx.x;
    const float4 v = *(const float4*)(x + (size_t)row * CD + tid * 4);

    float s  = v.x + v.y + v.z + v.w;
    float s2 = v.x*v.x + v.y*v.y + v.z*v.z + v.w*v.w;
    #pragma unroll
    for (int o = 16; o; o >>= 1) {
        s  += __shfl_xor_sync(~0u, s,  o);
        s2 += __shfl_xor_sync(~0u, s2, o);
    }
    if ((tid & 31) == 0) { red[(tid >> 5)*2] = s; red[(tid >> 5)*2 + 1] = s2; }
    __syncthreads();
    if (tid == 0) {
        float a = 0.f, b2 = 0.f;
        #pragma unroll
        for (int w = 0; w < 8; w++) { a += red[w*2]; b2 += red[w*2 + 1]; }
        float mu  = a * (1.f / CD);
        float var = b2 * (1.f / CD) - mu * mu;
        bc[0] = mu; bc[1] = rsqrtf(var + 1e-5f);
    }
    __syncthreads();
    const float mu = bc[0], rstd = bc[1];
    const float4 g4 = *(const float4*)(g + tid * 4);
    const float4 b4 = *(const float4*)(b + tid * 4);
    float4 o;
    o.x = (v.x - mu) * rstd * g4.x + b4.x;
    o.y = (v.y - mu) * rstd * g4.y + b4.y;
    o.z = (v.z - mu) * rstd * g4.z + b4.z;
    o.w = (v.w - mu) * rstd * g4.w + b4.w;
    *(float4*)(out + (size_t)row * CD + tid * 4) = o;
}

// ---------------------------------------------------------------------------
// TF32 tensor-core GEMM: C[M,N] = act(A[M,K] @ W[K,N] + bias) (+ res)
// 128x128 block tile, BK=16, double-buffered cp.async. 8 warps (2x4),
// warp tile 64x32, mma.m16n8k8.tf32. Conflict-free XOR-swizzled smem.
//   A smem: [m][k'] k' = k ^ (4*((m>>1)&3)), row stride 16
//   B smem: [k][n'] n' = n ^ (8*k),          row stride 128
// ---------------------------------------------------------------------------
__global__ __launch_bounds__(256) void gemm_tc(
    const float* __restrict__ A, const float* __restrict__ W,
    const float* __restrict__ bias, const float* __restrict__ res,
    float* __restrict__ Cc, int M, int N, int K, int act)
{
    __shared__ float As[2][128 * 16];
    __shared__ float Bs[2][16 * 128];

    const int tid  = threadIdx.x;
    const int lane = tid & 31;
    const int warp = tid >> 5;
    const int wm = warp & 1;        // 0..1  (64 rows each)
    const int wn = warp >> 1;       // 0..3  (32 cols each)
    const int bm = blockIdx.y * 128;
    const int bn = blockIdx.x * 128;

    const uint32_t sA = (uint32_t)__cvta_generic_to_shared(&As[0][0]);
    const uint32_t sB = (uint32_t)__cvta_generic_to_shared(&Bs[0][0]);

    // cp.async indices (fixed per thread)
    const int am  = (tid + 0)   >> 2;       // A chunk 0 row
    const int ak4 = (tid + 0)   &  3;
    const int am2 = (tid + 256) >> 2;       // A chunk 1 row
    const int ak42= (tid + 256) &  3;
    const int bk  = (tid + 0)   >> 5;       // B chunk 0 row
    const int bn4 = (tid + 0)   & 31;
    const int bk2 = (tid + 256) >> 5;       // B chunk 1 row
    const int bn42= (tid + 256) & 31;

    float acc[4][4][4];
    #pragma unroll
    for (int i = 0; i < 4; i++)
        #pragma unroll
        for (int j = 0; j < 4; j++)
            #pragma unroll
            for (int r = 0; r < 4; r++) acc[i][j][r] = 0.f;

    // stage issue macro-ish lambda
    auto issue = [&](int s, int k0) {
        // A: 512 chunks of 16B
        {
            uint32_t d = sA + (uint32_t)(s * 2048 + am * 16 + ((ak4 * 4) ^ (4 * ((am >> 1) & 3)))) * 4u;
            cp16(d, A + (size_t)(bm + am) * K + k0 + ak4 * 4);
            uint32_t d2 = sA + (uint32_t)(s * 2048 + am2 * 16 + ((ak42 * 4) ^ (4 * ((am2 >> 1) & 3)))) * 4u;
            cp16(d2, A + (size_t)(bm + am2) * K + k0 + ak42 * 4);
        }
        // B: 512 chunks
        {
            uint32_t d = sB + (uint32_t)(s * 2048 + bk * 128 + ((bn4 * 4) ^ (8 * bk))) * 4u;
            cp16(d, W + (size_t)(k0 + bk) * N + bn + bn4 * 4);
            uint32_t d2 = sB + (uint32_t)(s * 2048 + bk2 * 128 + ((bn42 * 4) ^ (8 * bk2))) * 4u;
            cp16(d2, W + (size_t)(k0 + bk2) * N + bn + bn42 * 4);
        }
    };

    issue(0, 0);  cp_commit();
    issue(1, 16); cp_commit();

    const int nK = K >> 4;
    const int r4 = lane >> 2;   // 0..7
    const int c4 = lane & 3;    // 0..3

    for (int kt = 0; kt < nK; kt++) {
        cp_wait<1>();
        __syncthreads();
        const int cur = kt & 1;
        const float* Ap = &As[cur][0];
        const float* Bp = &Bs[cur][0];

        #pragma unroll
        for (int k8 = 0; k8 < 2; k8++) {
            const int kb = k8 * 8 + c4;
            uint32_t af[4][4], bf[4][2];
            #pragma unroll
            for (int mf = 0; mf < 4; mf++) {
                const int m0 = wm * 64 + mf * 16 + r4;
                const int xm = 4 * ((m0 >> 1) & 3);
                const float* p = Ap + m0 * 16;
                af[mf][0] = f2tf32(p[kb ^ xm]);
                af[mf][1] = f2tf32(p[128 + (kb ^ xm)]);
                af[mf][2] = f2tf32(p[(kb + 4) ^ xm]);
                af[mf][3] = f2tf32(p[128 + ((kb + 4) ^ xm)]);
            }
            #pragma unroll
            for (int nf = 0; nf < 4; nf++) {
                const int n = wn * 32 + nf * 8 + r4;
                bf[nf][0] = f2tf32(Bp[kb * 128 + (n ^ (8 * kb))]);
                bf[nf][1] = f2tf32(Bp[(kb + 4) * 128 + (n ^ (8 * (kb + 4)))]);
            }
            #pragma unroll
            for (int mf = 0; mf < 4; mf++)
                #pragma unroll
                for (int nf = 0; nf < 4; nf++)
                    mma_tf32(acc[mf][nf], af[mf], bf[nf]);
        }
        __syncthreads();
        const int knext = (kt + 2) << 4;
        if (knext < K) issue(cur, knext);
        cp_commit();
    }

    // epilogue
    #pragma unroll
    for (int mf = 0; mf < 4; mf++) {
        #pragma unroll
        for (int nf = 0; nf < 4; nf++) {
            const int col = bn + wn * 32 + nf * 8 + c4 * 2;
            const float bx = bias[col], by = bias[col + 1];
            #pragma unroll
            for (int h = 0; h < 2; h++) {
                const int row = bm + wm * 64 + mf * 16 + r4 + h * 8;
                float ox = acc[mf][nf][h * 2 + 0] + bx;
                float oy = acc[mf][nf][h * 2 + 1] + by;
                if (act) {
                    ox *= 1.f / (1.f + __expf(-ox));
                    oy *= 1.f / (1.f + __expf(-oy));
                }
                const size_t off = (size_t)row * N + col;
                if (res) {
                    const float2 rr = *(const float2*)(res + off);
                    ox += rr.x; oy += rr.y;
                }
                float2 o; o.x = ox; o.y = oy;
                *(float2*)(Cc + off) = o;
            }
        }
    }
}

// ---------------------------------------------------------------------------
// Flash attention (fp32, causal). Same as R1.
// ---------------------------------------------------------------------------
#define ATTN_SMEM ((64*64*3 + 64*65) * 4)

__global__ __launch_bounds__(256) void attn_kernel(
    const float* __restrict__ Q, const float* __restrict__ Kg,
    const float* __restrict__ Vg, float* __restrict__ O)
{
    extern __shared__ float smem[];
    float* Qt = smem;
    float* Kt = Qt + 64 * 64;
    float* Vs = Kt + 64 * 64;
    float* Ps = Vs + 64 * 64;

    const int bh = blockIdx.y;
    const int b = bh >> 4, h = bh & 15;
    const int q0 = blockIdx.x * 64;
    const int tid = threadIdx.x;
    const int ty = tid >> 4, tx = tid & 15;
    const size_t base = (size_t)b * TD * CD + (size_t)h * HD;

    for (int idx = tid; idx < 64 * 64; idx += 256) {
        const int r = idx >> 6, d = idx & 63;
        Qt[d * 64 + r] = Q[base + (size_t)(q0 + r) * CD + d];
    }

    float m[4], l[4], acc[4][4];
    #pragma unroll
    for (int i = 0; i < 4; i++) {
        m[i] = -1e30f; l[i] = 0.f;
        #pragma unroll
        for (int j = 0; j < 4; j++) acc[i][j] = 0.f;
    }

    const int ktiles = blockIdx.x + 1;
    for (int kt = 0; kt < ktiles; kt++) {
        const int k0 = kt * 64;
        __syncthreads();
        for (int idx = tid; idx < 64 * 64; idx += 256) {
            const int r = idx >> 6, d = idx & 63;
            const size_t goff = base + (size_t)(k0 + r) * CD + d;
            Kt[d * 64 + r] = Kg[goff];
            Vs[idx]        = Vg[goff];
        }
        __syncthreads();

        float s[4][4];
        #pragma unroll
        for (int i = 0; i < 4; i++)
            #pragma unroll
            for (int j = 0; j < 4; j++) s[i][j] = 0.f;
        for (int d = 0; d < 64; d++) {
            float a[4], bb[4];
            #pragma unroll
            for (int i = 0; i < 4; i++) a[i]  = Qt[d * 64 + ty * 4 + i];
            #pragma unroll
            for (int j = 0; j < 4; j++) bb[j] = Kt[d * 64 + tx * 4 + j];
            #pragma unroll
            for (int i = 0; i < 4; i++)
                #pragma unroll
                for (int j = 0; j < 4; j++) s[i][j] += a[i] * bb[j];
        }
        #pragma unroll
        for (int i = 0; i < 4; i++)
            #pragma unroll
            for (int j = 0; j < 4; j++) s[i][j] *= 0.125f;

        if (kt == blockIdx.x) {
            #pragma unroll
            for (int i = 0; i < 4; i++)
                #pragma unroll
                for (int j = 0; j < 4; j++)
                    if (k0 + tx * 4 + j > q0 + ty * 4 + i) s[i][j] = -1e30f;
        }

        #pragma unroll
        for (int i = 0; i < 4; i++) {
            float rm = fmaxf(fmaxf(s[i][0], s[i][1]), fmaxf(s[i][2], s[i][3]));
            #pragma unroll
            for (int o = 8; o; o >>= 1) rm = fmaxf(rm, __shfl_xor_sync(~0u, rm, o));
            const float mn = fmaxf(m[i], rm);
            float rs = 0.f;
            #pragma unroll
            for (int j = 0; j < 4; j++) {
                const float p = __expf(s[i][j] - mn);
                Ps[(ty * 4 + i) * 65 + tx * 4 + j] = p;
                rs += p;
            }
            #pragma unroll
            for (int o = 8; o; o >>= 1) rs += __shfl_xor_sync(~0u, rs, o);
            const float fac = __expf(m[i] - mn);
            l[i] = l[i] * fac + rs;
            #pragma unroll
            for (int j = 0; j < 4; j++) acc[i][j] *= fac;
            m[i] = mn;
        }
        __syncthreads();

        for (int k = 0; k < 64; k++) {
            float p[4], vv[4];
            #pragma unroll
            for (int i = 0; i < 4; i++) p[i]  = Ps[(ty * 4 + i) * 65 + k];
            #pragma unroll
            for (int j = 0; j < 4; j++) vv[j] = Vs[k * 64 + tx * 4 + j];
            #pragma unroll
            for (int i = 0; i < 4; i++)
                #pragma unroll
                for (int j = 0; j < 4; j++) acc[i][j] += p[i] * vv[j];
        }
    }

    #pragma unroll
    for (int i = 0; i < 4; i++) {
        const float inv = 1.f / l[i];
        const size_t off = (size_t)(b * TD + q0 + ty * 4 + i) * CD + h * HD + tx * 4;
        #pragma unroll
        for (int j = 0; j < 4; j++) O[off + j] = acc[i][j] * inv;
    }
}

// ---------------------------------------------------------------------------
// Launch
// ---------------------------------------------------------------------------
extern "C" void kernel_launch(void* const* d_in, const int* in_sizes, int n_in,
                              void* d_out, int out_size)
{
    const float* x      = (const float*)d_in[0];
    const float* ln_a_g = (const float*)d_in[1];
    const float* ln_a_b = (const float*)d_in[2];
    const float* ln_b_g = (const float*)d_in[3];
    const float* ln_b_b = (const float*)d_in[4];
    const float* ln_c_g = (const float*)d_in[5];
    const float* ln_c_b = (const float*)d_in[6];
    const float* Wq = (const float*)d_in[7];  const float* bq = (const float*)d_in[8];
    const float* Wk = (const float*)d_in[9];  const float* bk = (const float*)d_in[10];
    const float* Wv = (const float*)d_in[11]; const float* bv = (const float*)d_in[12];
    const float* Wo = (const float*)d_in[13]; const float* bo = (const float*)d_in[14];
    const float* We = (const float*)d_in[15]; const float* be = (const float*)d_in[16];
    const float* Wd = (const float*)d_in[17]; const float* bd = (const float*)d_in[18];
    float* out = (float*)d_out;

    float *t, *q, *k, *v, *ctx, *x2, *h;
    cudaGetSymbolAddress((void**)&t,   g_t);
    cudaGetSymbolAddress((void**)&q,   g_q);
    cudaGetSymbolAddress((void**)&k,   g_k);
    cudaGetSymbolAddress((void**)&v,   g_v);
    cudaGetSymbolAddress((void**)&ctx, g_ctx);
    cudaGetSymbolAddress((void**)&x2,  g_x2);
    cudaGetSymbolAddress((void**)&h,   g_h);

    cudaFuncSetAttribute(attn_kernel, cudaFuncAttributeMaxDynamicSharedMemorySize,
                         ATTN_SMEM);

    // 1. t = LN_b(LN_a(x))
    ln2_kernel<<<NT, 256>>>(x, ln_a_g, ln_a_b, ln_b_g, ln_b_b, t);

    // 2. QKV projections (tf32 tensor cores)
    {
        dim3 grid(CD / 128, NT / 128);
        gemm_tc<<<grid, 256>>>(t, Wq, bq, nullptr, q, NT, CD, CD, 0);
        gemm_tc<<<grid, 256>>>(t, Wk, bk, nullptr, k, NT, CD, CD, 0);
        gemm_tc<<<grid, 256>>>(t, Wv, bv, nullptr, v, NT, CD, CD, 0);
    }

    // 3. causal attention
    {
        dim3 grid(TD / 64, BD * HN);
        attn_kernel<<<grid, 256, ATTN_SMEM>>>(q, k, v, ctx);
    }

    // 4. x2 = x + ctx @ Wo + bo
    {
        dim3 grid(CD / 128, NT / 128);
        gemm_tc<<<grid, 256>>>(ctx, Wo, bo, x, x2, NT, CD, CD, 0);
    }

    // 5. t = LN_c(x2)
    ln1_kernel<<<NT, 256>>>(x2, ln_c_g, ln_c_b, t);

    // 6. h = silu(t @ We + be)
    {
        dim3 grid(DFFD / 128, NT / 128);
        gemm_tc<<<grid, 256>>>(t, We, be, nullptr, h, NT, DFFD, CD, 1);
    }

    // 7. out = x2 + h @ Wd + bd
    {
        dim3 grid(CD / 128, NT / 128);
        gemm_tc<<<grid, 256>>>(h, Wd, bd, x2, out, NT, CD, DFFD, 0);
    }
}

// round 3
// speedup vs baseline: 4.0187x; 1.8918x over previous
#include <cuda_runtime.h>
#include <math.h>
#include <stdint.h>

// Problem dims
#define BD   2
#define TD   2048
#define CD   1024
#define HN   16
#define HD   64
#define DFFD 4096
#define NT   (BD * TD)   // 4096 tokens

// ---------------------------------------------------------------------------
// Scratch (device globals; no allocation allowed)
// ---------------------------------------------------------------------------
__device__ float g_t  [(size_t)NT * CD];
__device__ float g_q  [(size_t)NT * CD];
__device__ float g_k  [(size_t)NT * CD];
__device__ float g_v  [(size_t)NT * CD];
__device__ float g_ctx[(size_t)NT * CD];
__device__ float g_x2 [(size_t)NT * CD];
__device__ float g_h  [(size_t)NT * DFFD];

// ---------------------------------------------------------------------------
// Helpers
// ---------------------------------------------------------------------------
__device__ __forceinline__ void cp16(uint32_t smem_dst, const void* gptr) {
    asm volatile("cp.async.cg.shared.global [%0], [%1], 16;\n"
                 :: "r"(smem_dst), "l"(gptr));
}
__device__ __forceinline__ void cp_commit() {
    asm volatile("cp.async.commit_group;\n" ::: "memory");
}
template <int N>
__device__ __forceinline__ void cp_wait() {
    asm volatile("cp.async.wait_group %0;\n" :: "n"(N) : "memory");
}

__device__ __forceinline__ void mma_tf32(float* c, const uint32_t* a, const uint32_t* b) {
    asm volatile(
        "mma.sync.aligned.m16n8k8.row.col.f32.tf32.tf32.f32 "
        "{%0,%1,%2,%3},{%4,%5,%6,%7},{%8,%9},{%0,%1,%2,%3};"
        : "+f"(c[0]), "+f"(c[1]), "+f"(c[2]), "+f"(c[3])
        : "r"(a[0]), "r"(a[1]), "r"(a[2]), "r"(a[3]), "r"(b[0]), "r"(b[1]));
}

// ---------------------------------------------------------------------------
// Fused double LayerNorm
// ---------------------------------------------------------------------------
__global__ __launch_bounds__(256) void ln2_kernel(
    const float* __restrict__ x,
    const float* __restrict__ ga, const float* __restrict__ ba,
    const float* __restrict__ gb, const float* __restrict__ bb,
    float* __restrict__ out)
{
    __shared__ float red[16];
    __shared__ float bc[2];
    const int row = blockIdx.x, tid = threadIdx.x;
    const float4 v = *(const float4*)(x + (size_t)row * CD + tid * 4);

    float s  = v.x + v.y + v.z + v.w;
    float s2 = v.x*v.x + v.y*v.y + v.z*v.z + v.w*v.w;
    #pragma unroll
    for (int o = 16; o; o >>= 1) {
        s  += __shfl_xor_sync(~0u, s,  o);
        s2 += __shfl_xor_sync(~0u, s2, o);
    }
    if ((tid & 31) == 0) { red[(tid >> 5)*2] = s; red[(tid >> 5)*2 + 1] = s2; }
    __syncthreads();
    if (tid == 0) {
        float a = 0.f, b2 = 0.f;
        #pragma unroll
        for (int w = 0; w < 8; w++) { a += red[w*2]; b2 += red[w*2 + 1]; }
        float mu  = a * (1.f / CD);
        float var = b2 * (1.f / CD) - mu * mu;
        bc[0] = mu; bc[1] = rsqrtf(var + 1e-5f);
    }
    __syncthreads();
    float mu = bc[0], rstd = bc[1];
    __syncthreads();

    const float4 g4 = *(const float4*)(ga + tid * 4);
    const float4 b4 = *(const float4*)(ba + tid * 4);
    float y[4];
    y[0] = (v.x - mu) * rstd * g4.x + b4.x;
    y[1] = (v.y - mu) * rstd * g4.y + b4.y;
    y[2] = (v.z - mu) * rstd * g4.z + b4.z;
    y[3] = (v.w - mu) * rstd * g4.w + b4.w;

    s  = y[0] + y[1] + y[2] + y[3];
    s2 = y[0]*y[0] + y[1]*y[1] + y[2]*y[2] + y[3]*y[3];
    #pragma unroll
    for (int o = 16; o; o >>= 1) {
        s  += __shfl_xor_sync(~0u, s,  o);
        s2 += __shfl_xor_sync(~0u, s2, o);
    }
    if ((tid & 31) == 0) { red[(tid >> 5)*2] = s; red[(tid >> 5)*2 + 1] = s2; }
    __syncthreads();
    if (tid == 0) {
        float a = 0.f, b2 = 0.f;
        #pragma unroll
        for (int w = 0; w < 8; w++) { a += red[w*2]; b2 += red[w*2 + 1]; }
        float mu2  = a * (1.f / CD);
        float var2 = b2 * (1.f / CD) - mu2 * mu2;
        bc[0] = mu2; bc[1] = rsqrtf(var2 + 1e-5f);
    }
    __syncthreads();
    mu = bc[0]; rstd = bc[1];

    const float4 g24 = *(const float4*)(gb + tid * 4);
    const float4 b24 = *(const float4*)(bb + tid * 4);
    float4 o;
    o.x = (y[0] - mu) * rstd * g24.x + b24.x;
    o.y = (y[1] - mu) * rstd * g24.y + b24.y;
    o.z = (y[2] - mu) * rstd * g24.z + b24.z;
    o.w = (y[3] - mu) * rstd * g24.w + b24.w;
    *(float4*)(out + (size_t)row * CD + tid * 4) = o;
}

__global__ __launch_bounds__(256) void ln1_kernel(
    const float* __restrict__ x,
    const float* __restrict__ g, const float* __restrict__ b,
    float* __restrict__ out)
{
    __shared__ float red[16];
    __shared__ float bc[2];
    const int row = blockIdx.x, tid = threadIdx.x;
    const float4 v = *(const float4*)(x + (size_t)row * CD + tid * 4);

    float s  = v.x + v.y + v.z + v.w;
    float s2 = v.x*v.x + v.y*v.y + v.z*v.z + v.w*v.w;
    #pragma unroll
    for (int o = 16; o; o >>= 1) {
        s  += __shfl_xor_sync(~0u, s,  o);
        s2 += __shfl_xor_sync(~0u, s2, o);
    }
    if ((tid & 31) == 0) { red[(tid >> 5)*2] = s; red[(tid >> 5)*2 + 1] = s2; }
    __syncthreads();
    if (tid == 0) {
        float a = 0.f, b2 = 0.f;
        #pragma unroll
        for (int w = 0; w < 8; w++) { a += red[w*2]; b2 += red[w*2 + 1]; }
        float mu  = a * (1.f / CD);
        float var = b2 * (1.f / CD) - mu * mu;
        bc[0] = mu; bc[1] = rsqrtf(var + 1e-5f);
    }
    __syncthreads();
    const float mu = bc[0], rstd = bc[1];
    const float4 g4 = *(const float4*)(g + tid * 4);
    const float4 b4 = *(const float4*)(b + tid * 4);
    float4 o;
    o.x = (v.x - mu) * rstd * g4.x + b4.x;
    o.y = (v.y - mu) * rstd * g4.y + b4.y;
    o.z = (v.z - mu) * rstd * g4.z + b4.z;
    o.w = (v.w - mu) * rstd * g4.w + b4.w;
    *(float4*)(out + (size_t)row * CD + tid * 4) = o;
}

// ---------------------------------------------------------------------------
// TF32 tensor-core GEMM (raw-bits tf32: no cvt in the hot loop)
// ---------------------------------------------------------------------------
__global__ __launch_bounds__(256) void gemm_tc(
    const float* __restrict__ A, const float* __restrict__ W,
    const float* __restrict__ bias, const float* __restrict__ res,
    float* __restrict__ Cc, int M, int N, int K, int act)
{
    __shared__ float As[2][128 * 16];
    __shared__ float Bs[2][16 * 128];

    const int tid  = threadIdx.x;
    const int lane = tid & 31;
    const int warp = tid >> 5;
    const int wm = warp & 1;
    const int wn = warp >> 1;
    const int bm = blockIdx.y * 128;
    const int bn = blockIdx.x * 128;

    const uint32_t sA = (uint32_t)__cvta_generic_to_shared(&As[0][0]);
    const uint32_t sB = (uint32_t)__cvta_generic_to_shared(&Bs[0][0]);

    const int am  = (tid + 0)   >> 2;
    const int ak4 = (tid + 0)   &  3;
    const int am2 = (tid + 256) >> 2;
    const int ak42= (tid + 256) &  3;
    const int bk  = (tid + 0)   >> 5;
    const int bn4 = (tid + 0)   & 31;
    const int bk2 = (tid + 256) >> 5;
    const int bn42= (tid + 256) & 31;

    float acc[4][4][4];
    #pragma unroll
    for (int i = 0; i < 4; i++)
        #pragma unroll
        for (int j = 0; j < 4; j++)
            #pragma unroll
            for (int r = 0; r < 4; r++) acc[i][j][r] = 0.f;

    auto issue = [&](int s, int k0) {
        {
            uint32_t d = sA + (uint32_t)(s * 2048 + am * 16 + ((ak4 * 4) ^ (4 * ((am >> 1) & 3)))) * 4u;
            cp16(d, A + (size_t)(bm + am) * K + k0 + ak4 * 4);
            uint32_t d2 = sA + (uint32_t)(s * 2048 + am2 * 16 + ((ak42 * 4) ^ (4 * ((am2 >> 1) & 3)))) * 4u;
            cp16(d2, A + (size_t)(bm + am2) * K + k0 + ak42 * 4);
        }
        {
            uint32_t d = sB + (uint32_t)(s * 2048 + bk * 128 + ((bn4 * 4) ^ (8 * bk))) * 4u;
            cp16(d, W + (size_t)(k0 + bk) * N + bn + bn4 * 4);
            uint32_t d2 = sB + (uint32_t)(s * 2048 + bk2 * 128 + ((bn42 * 4) ^ (8 * bk2))) * 4u;
            cp16(d2, W + (size_t)(k0 + bk2) * N + bn + bn42 * 4);
        }
    };

    issue(0, 0);  cp_commit();
    issue(1, 16); cp_commit();

    const int nK = K >> 4;
    const int r4 = lane >> 2;
    const int c4 = lane & 3;

    for (int kt = 0; kt < nK; kt++) {
        cp_wait<1>();
        __syncthreads();
        const int cur = kt & 1;
        const float* Ap = &As[cur][0];
        const float* Bp = &Bs[cur][0];

        #pragma unroll
        for (int k8 = 0; k8 < 2; k8++) {
            const int kb = k8 * 8 + c4;
            uint32_t af[4][4], bf[4][2];
            #pragma unroll
            for (int mf = 0; mf < 4; mf++) {
                const int m0 = wm * 64 + mf * 16 + r4;
                const int xm = 4 * ((m0 >> 1) & 3);
                const float* p = Ap + m0 * 16;
                af[mf][0] = __float_as_uint(p[kb ^ xm]);
                af[mf][1] = __float_as_uint(p[128 + (kb ^ xm)]);
                af[mf][2] = __float_as_uint(p[(kb + 4) ^ xm]);
                af[mf][3] = __float_as_uint(p[128 + ((kb + 4) ^ xm)]);
            }
            #pragma unroll
            for (int nf = 0; nf < 4; nf++) {
                const int n = wn * 32 + nf * 8 + r4;
                bf[nf][0] = __float_as_uint(Bp[kb * 128 + (n ^ (8 * kb))]);
                bf[nf][1] = __float_as_uint(Bp[(kb + 4) * 128 + (n ^ (8 * (kb + 4)))]);
            }
            #pragma unroll
            for (int mf = 0; mf < 4; mf++)
                #pragma unroll
                for (int nf = 0; nf < 4; nf++)
                    mma_tf32(acc[mf][nf], af[mf], bf[nf]);
        }
        __syncthreads();
        const int knext = (kt + 2) << 4;
        if (knext < K) issue(cur, knext);
        cp_commit();
    }

    #pragma unroll
    for (int mf = 0; mf < 4; mf++) {
        #pragma unroll
        for (int nf = 0; nf < 4; nf++) {
            const int col = bn + wn * 32 + nf * 8 + c4 * 2;
            const float bx = bias[col], by = bias[col + 1];
            #pragma unroll
            for (int h = 0; h < 2; h++) {
                const int row = bm + wm * 64 + mf * 16 + r4 + h * 8;
                float ox = acc[mf][nf][h * 2 + 0] + bx;
                float oy = acc[mf][nf][h * 2 + 1] + by;
                if (act) {
                    ox *= 1.f / (1.f + __expf(-ox));
                    oy *= 1.f / (1.f + __expf(-oy));
                }
                const size_t off = (size_t)row * N + col;
                if (res) {
                    const float2 rr = *(const float2*)(res + off);
                    ox += rr.x; oy += rr.y;
                }
                float2 o; o.x = ox; o.y = oy;
                *(float2*)(Cc + off) = o;
            }
        }
    }
}

// ---------------------------------------------------------------------------
// Flash attention on tensor cores (tf32 mma, causal).
// Grid (T/64, B*H), 128 threads (4 warps x 16 rows). K/V double-buffered.
// Smem pads: Q/K/P stride 68 (banks 4r+c bijective), V stride 72 (8k+n).
// ---------------------------------------------------------------------------
#define PQ 68
#define PV 72
#define ATTN_SMEM ((64*PQ + 2*64*PQ + 2*64*PV + 4*16*PQ) * 4)

__global__ __launch_bounds__(128) void attn_tc(
    const float* __restrict__ Q, const float* __restrict__ Kg,
    const float* __restrict__ Vg, float* __restrict__ O)
{
    extern __shared__ float sm[];
    float* Qs = sm;                       // [64][PQ]
    float* Ks = Qs + 64 * PQ;             // [2][64][PQ]
    float* Vs = Ks + 2 * 64 * PQ;         // [2][64][PV]
    float* Ps = Vs + 2 * 64 * PV;         // [4][16][PQ]

    const int bh = blockIdx.y;
    const int b = bh >> 4, h = bh & 15;
    const int qt = blockIdx.x;
    const int q0 = qt * 64;
    const int tid = threadIdx.x;
    const int lane = tid & 31;
    const int warp = tid >> 5;
    const int r4 = lane >> 2;   // 0..7
    const int c4 = lane & 3;    // 0..3
    const size_t base = (size_t)b * TD * CD + (size_t)h * HD;

    const uint32_t sQ = (uint32_t)__cvta_generic_to_shared(Qs);
    const uint32_t sK = (uint32_t)__cvta_generic_to_shared(Ks);
    const uint32_t sV = (uint32_t)__cvta_generic_to_shared(Vs);

    // ---- issue Q tile + KV tile 0 (group 0) ----
    #pragma unroll
    for (int i = 0; i < 8; i++) {
        const int idx = tid + i * 128;          // 1024 chunks
        const int row = idx >> 4, cc = idx & 15;
        cp16(sQ + (uint32_t)(row * PQ + cc * 4) * 4u,
             Q + base + (size_t)(q0 + row) * CD + cc * 4);
    }
    auto issue_kv = [&](int buf, int k0) {
        #pragma unroll
        for (int i = 0; i < 8; i++) {
            const int idx = tid + i * 128;
            const int row = idx >> 4, cc = idx & 15;
            const size_t g = base + (size_t)(k0 + row) * CD + cc * 4;
            cp16(sK + (uint32_t)(buf * 64 * PQ + row * PQ + cc * 4) * 4u, Kg + g);
            cp16(sV + (uint32_t)(buf * 64 * PV + row * PV + cc * 4) * 4u, Vg + g);
        }
    };
    issue_kv(0, 0);
    cp_commit();
    if (qt >= 1) { issue_kv(1, 64); cp_commit(); }

    uint32_t qf[8][4];
    float oacc[8][4];
    #pragma unroll
    for (int nt = 0; nt < 8; nt++)
        #pragma unroll
        for (int r = 0; r < 4; r++) oacc[nt][r] = 0.f;
    float m0 = -1e30f, m1 = -1e30f, l0 = 0.f, l1 = 0.f;

    float* Pw = Ps + warp * 16 * PQ;

    for (int kt = 0; kt <= qt; kt++) {
        if (kt + 1 <= qt) cp_wait<1>(); else cp_wait<0>();
        __syncthreads();
        const int cur = kt & 1;
        const float* Kp = Ks + cur * 64 * PQ;
        const float* Vp = Vs + cur * 64 * PV;

        if (kt == 0) {
            // preload Q fragments, folding in 1/sqrt(HD)
            const float* qp = Qs + (warp * 16 + r4) * PQ;
            #pragma unroll
            for (int ks = 0; ks < 8; ks++) {
                const int c = ks * 8 + c4;
                qf[ks][0] = __float_as_uint(qp[c] * 0.125f);
                qf[ks][1] = __float_as_uint(qp[8 * PQ + c] * 0.125f);
                qf[ks][2] = __float_as_uint(qp[c + 4] * 0.125f);
                qf[ks][3] = __float_as_uint(qp[8 * PQ + c + 4] * 0.125f);
            }
        }

        // ---- S = Q K^T ----
        float sacc[8][4];
        #pragma unroll
        for (int nt = 0; nt < 8; nt++)
            #pragma unroll
            for (int r = 0; r < 4; r++) sacc[nt][r] = 0.f;

        #pragma unroll
        for (int ks = 0; ks < 8; ks++) {
            const int k = ks * 8 + c4;
            #pragma unroll
            for (int nt = 0; nt < 8; nt++) {
                const int n = nt * 8 + r4;
                uint32_t bf[2];
                bf[0] = __float_as_uint(Kp[n * PQ + k]);
                bf[1] = __float_as_uint(Kp[n * PQ + k + 4]);
                mma_tf32(sacc[nt], qf[ks], bf);
            }
        }

        // causal mask on diagonal tile
        if (kt == qt) {
            const int row0 = warp * 16 + r4;
            #pragma unroll
            for (int nt = 0; nt < 8; nt++) {
                const int cb = nt * 8 + 2 * c4;
                if (cb + 0 > row0)     sacc[nt][0] = -1e30f;
                if (cb + 1 > row0)     sacc[nt][1] = -1e30f;
                if (cb + 0 > row0 + 8) sacc[nt][2] = -1e30f;
                if (cb + 1 > row0 + 8) sacc[nt][3] = -1e30f;
            }
        }

        // ---- online softmax ----
        float rm0 = -1e30f, rm1 = -1e30f;
        #pragma unroll
        for (int nt = 0; nt < 8; nt++) {
            rm0 = fmaxf(rm0, fmaxf(sacc[nt][0], sacc[nt][1]));
            rm1 = fmaxf(rm1, fmaxf(sacc[nt][2], sacc[nt][3]));
        }
        rm0 = fmaxf(rm0, __shfl_xor_sync(~0u, rm0, 1));
        rm0 = fmaxf(rm0, __shfl_xor_sync(~0u, rm0, 2));
        rm1 = fmaxf(rm1, __shfl_xor_sync(~0u, rm1, 1));
        rm1 = fmaxf(rm1, __shfl_xor_sync(~0u, rm1, 2));

        const float mn0 = fmaxf(m0, rm0), mn1 = fmaxf(m1, rm1);
        const float f0 = __expf(m0 - mn0), f1 = __expf(m1 - mn1);
        m0 = mn0; m1 = mn1;

        float rs0 = 0.f, rs1 = 0.f;
        #pragma unroll
        for (int nt = 0; nt < 8; nt++) {
            float p0 = __expf(sacc[nt][0] - mn0);
            float p1 = __expf(sacc[nt][1] - mn0);
            float p2 = __expf(sacc[nt][2] - mn1);
            float p3 = __expf(sacc[nt][3] - mn1);
            rs0 += p0 + p1; rs1 += p2 + p3;
            float2 w0; w0.x = p0; w0.y = p1;
            float2 w1; w1.x = p2; w1.y = p3;
            *(float2*)(Pw + r4 * PQ + nt * 8 + 2 * c4)       = w0;
            *(float2*)(Pw + (r4 + 8) * PQ + nt * 8 + 2 * c4) = w1;
        }
        rs0 += __shfl_xor_sync(~0u, rs0, 1);
        rs0 += __shfl_xor_sync(~0u, rs0, 2);
        rs1 += __shfl_xor_sync(~0u, rs1, 1);
        rs1 += __shfl_xor_sync(~0u, rs1, 2);
        l0 = l0 * f0 + rs0;
        l1 = l1 * f1 + rs1;

        #pragma unroll
        for (int nt = 0; nt < 8; nt++) {
            oacc[nt][0] *= f0; oacc[nt][1] *= f0;
            oacc[nt][2] *= f1; oacc[nt][3] *= f1;
        }
        __syncwarp();

        // ---- O += P V ----
        #pragma unroll
        for (int ks = 0; ks < 8; ks++) {
            const int c = ks * 8 + c4;
            uint32_t af[4];
            af[0] = __float_as_uint(Pw[r4 * PQ + c]);
            af[1] = __float_as_uint(Pw[(r4 + 8) * PQ + c]);
            af[2] = __float_as_uint(Pw[r4 * PQ + c + 4]);
            af[3] = __float_as_uint(Pw[(r4 + 8) * PQ + c + 4]);
            #pragma unroll
            for (int nt = 0; nt < 8; nt++) {
                const int n = nt * 8 + r4;
                uint32_t bf[2];
                bf[0] = __float_as_uint(Vp[c * PV + n]);        // wrong? k index
                bf[1] = __float_as_uint(Vp[(c + 4) * PV + n]);  // see note below
                mma_tf32(oacc[nt], af, bf);
            }
        }

        // prefetch kt+2 into this buffer (done computing with it)
        __syncthreads();
        if (kt + 2 <= qt) { issue_kv(cur, (kt + 2) * 64); cp_commit(); }
    }

    // ---- epilogue ----
    const float inv0 = 1.f / l0, inv1 = 1.f / l1;
    const int row0 = q0 + warp * 16 + r4;
    #pragma unroll
    for (int nt = 0; nt < 8; nt++) {
        const int col = h * HD + nt * 8 + 2 * c4;
        float2 o0, o1;
        o0.x = oacc[nt][0] * inv0; o0.y = oacc[nt][1] * inv0;
        o1.x = oacc[nt][2] * inv1; o1.y = oacc[nt][3] * inv1;
        *(float2*)(O + (size_t)(b * TD + row0) * CD + col)     = o0;
        *(float2*)(O + (size_t)(b * TD + row0 + 8) * CD + col) = o1;
    }
}

// NOTE on the PV B-fragment: mma.row.col B element (k,n) must come from
// V[key=k][d=n]; Vp is stored [key][PV] row-major, and k = ks*8 + (lane&3),
// so Vp[k * PV + n] is exactly V[key=k][d=n]. The "c" variable equals k here.

// ---------------------------------------------------------------------------
// Launch
// ---------------------------------------------------------------------------
extern "C" void kernel_launch(void* const* d_in, const int* in_sizes, int n_in,
                              void* d_out, int out_size)
{
    const float* x      = (const float*)d_in[0];
    const float* ln_a_g = (const float*)d_in[1];
    const float* ln_a_b = (const float*)d_in[2];
    const float* ln_b_g = (const float*)d_in[3];
    const float* ln_b_b = (const float*)d_in[4];
    const float* ln_c_g = (const float*)d_in[5];
    const float* ln_c_b = (const float*)d_in[6];
    const float* Wq = (const float*)d_in[7];  const float* bq = (const float*)d_in[8];
    const float* Wk = (const float*)d_in[9];  const float* bk = (const float*)d_in[10];
    const float* Wv = (const float*)d_in[11]; const float* bv = (const float*)d_in[12];
    const float* Wo = (const float*)d_in[13]; const float* bo = (const float*)d_in[14];
    const float* We = (const float*)d_in[15]; const float* be = (const float*)d_in[16];
    const float* Wd = (const float*)d_in[17]; const float* bd = (const float*)d_in[18];
    float* out = (float*)d_out;

    float *t, *q, *k, *v, *ctx, *x2, *h;
    cudaGetSymbolAddress((void**)&t,   g_t);
    cudaGetSymbolAddress((void**)&q,   g_q);
    cudaGetSymbolAddress((void**)&k,   g_k);
    cudaGetSymbolAddress((void**)&v,   g_v);
    cudaGetSymbolAddress((void**)&ctx, g_ctx);
    cudaGetSymbolAddress((void**)&x2,  g_x2);
    cudaGetSymbolAddress((void**)&h,   g_h);

    cudaFuncSetAttribute(attn_tc, cudaFuncAttributeMaxDynamicSharedMemorySize,
                         ATTN_SMEM);

    // 1. t = LN_b(LN_a(x))
    ln2_kernel<<<NT, 256>>>(x, ln_a_g, ln_a_b, ln_b_g, ln_b_b, t);

    // 2. QKV projections
    {
        dim3 grid(CD / 128, NT / 128);
        gemm_tc<<<grid, 256>>>(t, Wq, bq, nullptr, q, NT, CD, CD, 0);
        gemm_tc<<<grid, 256>>>(t, Wk, bk, nullptr, k, NT, CD, CD, 0);
        gemm_tc<<<grid, 256>>>(t, Wv, bv, nullptr, v, NT, CD, CD, 0);
    }

    // 3. causal attention (tensor cores)
    {
        dim3 grid(TD / 64, BD * HN);
        attn_tc<<<grid, 128, ATTN_SMEM>>>(q, k, v, ctx);
    }

    // 4. x2 = x + ctx @ Wo + bo
    {
        dim3 grid(CD / 128, NT / 128);
        gemm_tc<<<grid, 256>>>(ctx, Wo, bo, x, x2, NT, CD, CD, 0);
    }

    // 5. t = LN_c(x2)
    ln1_kernel<<<NT, 256>>>(x2, ln_c_g, ln_c_b, t);

    // 6. h = silu(t @ We + be)
    {
        dim3 grid(DFFD / 128, NT / 128);
        gemm_tc<<<grid, 256>>>(t, We, be, nullptr, h, NT, DFFD, CD, 1);
    }

    // 7. out = x2 + h @ Wd + bd
    {
        dim3 grid(CD / 128, NT / 128);
        gemm_tc<<<grid, 256>>>(h, Wd, bd, x2, out, NT, CD, DFFD, 0);
    }
}